// round 1
// baseline (speedup 1.0000x reference)
#include <cuda_runtime.h>
#include <cstdint>

// Problem constants
#define B_IMG   4
#define C_CH    256
#define L_SEQ   4096
#define NSEQ    16          // 4 chunks * B
#define T_TOK   65536       // NSEQ * L_SEQ
#define DM      64
#define DI      128
#define NSTATE  16
#define CLCH    128         // scan chunk length
#define NCH     32          // chunks per sequence
#define EPS     1e-5f

// ---------------- scratch (static device allocations) ----------------
__device__ float g_xs   [T_TOK * DM];        // layernormed, chunked input (16,L,64)
__device__ float g_xcpre[T_TOK * DI];        // xz[:, :128] pre-conv
__device__ float g_z    [T_TOK * DI];        // silu(z)
__device__ float g_xc   [T_TOK * DI];        // silu(conv)
__device__ float g_xdbl [T_TOK * 36];        // x_proj output
__device__ float g_dt   [T_TOK * DI];        // softplus dt
__device__ float g_ypart[T_TOK * DI];        // scan partial (zero-init state)
__device__ float g_y    [T_TOK * DI];        // gated scan output
__device__ float g_hend [NSEQ * NCH * DI * NSTATE];
__device__ float g_h0   [NSEQ * NCH * DI * NSTATE];
__device__ float g_dtsum[NSEQ * NCH * DI];
__device__ float g_ym   [T_TOK * DM];
__device__ float g_yn   [T_TOK * DM];
__device__ float g_h1   [T_TOK * 256];
__device__ float g_ym2  [T_TOK * DM];
__device__ float g_xi   [B_IMG * L_SEQ * C_CH];
__device__ float g_A2   [DI * NSTATE];       // A * log2(e)

// ---------------- small helpers ----------------
__device__ __forceinline__ float siluf(float v) { return v / (1.0f + expf(-v)); }

// ---------------- A2 precompute ----------------
__global__ void a2_kernel(const float* __restrict__ A_log, float* __restrict__ A2)
{
    int i = blockIdx.x * blockDim.x + threadIdx.x;
    if (i < DI * NSTATE) A2[i] = -expf(A_log[i]) * 1.44269504088896340736f;
}

// ---------------- LayerNorm over C=256 + chunk rearrange ----------------
// x (B,C,H,W) -> g_xs laid out as (16, L, 64), seq = chunk*4 + b, channel c = chunk*64+d
__global__ void __launch_bounds__(256) ln1_kernel(const float* __restrict__ x,
                                                  const float* __restrict__ g,
                                                  const float* __restrict__ bb,
                                                  float* __restrict__ xs)
{
    __shared__ float sm[32][257];
    const int b  = blockIdx.y;
    const int l0 = blockIdx.x * 32;
    const int lane = threadIdx.x & 31;
    const int w    = threadIdx.x >> 5;
    const float* xb = x + (size_t)b * C_CH * L_SEQ;

    for (int c = w; c < 256; c += 8)
        sm[lane][c] = xb[(size_t)c * L_SEQ + l0 + lane];
    __syncthreads();

    for (int tk = 0; tk < 4; tk++) {
        int l = w * 4 + tk;
        float s = 0.f, s2 = 0.f;
        #pragma unroll
        for (int j = 0; j < 8; j++) {
            float v = sm[l][lane + 32 * j];
            s += v; s2 += v * v;
        }
        #pragma unroll
        for (int o = 16; o; o >>= 1) {
            s  += __shfl_xor_sync(0xffffffffu, s, o);
            s2 += __shfl_xor_sync(0xffffffffu, s2, o);
        }
        float mean = s * (1.0f / 256.0f);
        float var  = s2 * (1.0f / 256.0f) - mean * mean;
        float rs   = rsqrtf(var + EPS);
        #pragma unroll
        for (int j = 0; j < 8; j++) {
            int c = lane + 32 * j;
            float v = (sm[l][c] - mean) * rs * g[c] + bb[c];
            int seq = (c >> 6) * 4 + b;
            int d   = c & 63;
            xs[((size_t)seq * L_SEQ + l0 + l) * DM + d] = v;
        }
    }
}

// ---------------- generic tiled GEMM: C = A(M,K) * W(N,K)^T ----------------
struct EpiArgs {
    const float* b0;
    const float* b1;
    const float* b2;
    const float* b3;
    float* out2;
};

#define EPI_STORE 0
#define EPI_SPLIT 1
#define EPI_GELU  2
#define EPI_SKIP  3
#define EPI_BN    4

template<int K, int EPI>
__global__ void __launch_bounds__(256) gemm_k(const float* __restrict__ A,
                                              const float* __restrict__ W,
                                              float* __restrict__ C,
                                              int M, int N, EpiArgs ea)
{
    __shared__ float As[16][68];
    __shared__ float Ws[16][68];
    const int tid = threadIdx.x;
    const int bm = blockIdx.y * 64;
    const int bn = blockIdx.x * 64;
    const int tx = tid & 15, ty = tid >> 4;
    const int r  = tid >> 2;
    const int c4 = (tid & 3) << 2;
    const bool wok = (bn + r) < N;

    float acc[4][4];
    #pragma unroll
    for (int i = 0; i < 4; i++)
        #pragma unroll
        for (int j = 0; j < 4; j++) acc[i][j] = 0.f;

    const float* Aptr = A + (size_t)(bm + r) * K + c4;
    const float* Wptr = W + (size_t)(bn + r) * K + c4;

    #pragma unroll 1
    for (int k0 = 0; k0 < K; k0 += 16) {
        float4 av = *(const float4*)(Aptr + k0);
        float4 wv = make_float4(0.f, 0.f, 0.f, 0.f);
        if (wok) wv = *(const float4*)(Wptr + k0);
        As[c4 + 0][r] = av.x; As[c4 + 1][r] = av.y; As[c4 + 2][r] = av.z; As[c4 + 3][r] = av.w;
        Ws[c4 + 0][r] = wv.x; Ws[c4 + 1][r] = wv.y; Ws[c4 + 2][r] = wv.z; Ws[c4 + 3][r] = wv.w;
        __syncthreads();
        #pragma unroll
        for (int kk = 0; kk < 16; kk++) {
            float4 a4 = *(const float4*)&As[kk][ty << 2];
            float4 b4 = *(const float4*)&Ws[kk][tx << 2];
            float ar[4] = {a4.x, a4.y, a4.z, a4.w};
            float br[4] = {b4.x, b4.y, b4.z, b4.w};
            #pragma unroll
            for (int i = 0; i < 4; i++)
                #pragma unroll
                for (int j = 0; j < 4; j++)
                    acc[i][j] = fmaf(ar[i], br[j], acc[i][j]);
        }
        __syncthreads();
    }

    #pragma unroll
    for (int i = 0; i < 4; i++) {
        int m = bm + (ty << 2) + i;
        #pragma unroll
        for (int j = 0; j < 4; j++) {
            int n = bn + (tx << 2) + j;
            if (n >= N) continue;
            float v = acc[i][j];
            if (EPI == EPI_STORE) {
                C[(size_t)m * N + n] = v;
            } else if (EPI == EPI_SPLIT) {
                if (n < 128) C[(size_t)m * 128 + n] = v;
                else         ea.out2[(size_t)m * 128 + (n - 128)] = siluf(v);
            } else if (EPI == EPI_GELU) {
                v += ea.b0[n];
                v = 0.5f * v * (1.0f + erff(v * 0.70710678118654752f));
                C[(size_t)m * N + n] = v;
            } else if (EPI == EPI_SKIP) {
                v += ea.b0[n] + ea.b2[0] * ea.b1[(size_t)m * DM + n];
                C[(size_t)m * N + n] = v;
            } else { // EPI_BN: transposed store to (B,C,H,W) + BN affine + silu
                float sc = ea.b0[n] * rsqrtf(ea.b3[n] + EPS);
                float sh = ea.b1[n] - ea.b2[n] * sc;
                v = siluf(v * sc + sh);
                int bb = m >> 12, l = m & 4095;
                C[(((size_t)bb * 256 + n) << 12) + l] = v;
            }
        }
    }
}

// ---------------- depthwise causal conv (KC=4) + bias + silu ----------------
__global__ void conv_kernel(const float* __restrict__ xcpre, const float* __restrict__ Wc,
                            const float* __restrict__ bc, float* __restrict__ xcout)
{
    int idx = blockIdx.x * blockDim.x + threadIdx.x;   // T_TOK * 32
    int t = idx >> 5;
    int q = (idx & 31) << 2;                            // channel base
    int l = t & (L_SEQ - 1);

    float wjc[4][4];                                    // [tap][channel]
    #pragma unroll
    for (int c = 0; c < 4; c++) {
        float4 w = __ldg((const float4*)(Wc + (q + c) * 4));
        wjc[0][c] = w.x; wjc[1][c] = w.y; wjc[2][c] = w.z; wjc[3][c] = w.w;
    }
    float4 b4 = __ldg((const float4*)(bc + q));
    float o0 = b4.x, o1 = b4.y, o2 = b4.z, o3 = b4.w;
    #pragma unroll
    for (int j = 0; j < 4; j++) {
        int lj = l - 3 + j;
        if (lj >= 0) {
            float4 v = __ldg((const float4*)(xcpre + (size_t)(t - 3 + j) * DI + q));
            o0 = fmaf(v.x, wjc[j][0], o0);
            o1 = fmaf(v.y, wjc[j][1], o1);
            o2 = fmaf(v.z, wjc[j][2], o2);
            o3 = fmaf(v.w, wjc[j][3], o3);
        }
    }
    float4 out = make_float4(siluf(o0), siluf(o1), siluf(o2), siluf(o3));
    *(float4*)(xcout + (size_t)t * DI + q) = out;
}

// ---------------- dt = softplus(x_dbl[:, :4] @ W_dt^T + b_dt) ----------------
__global__ void dt_kernel(const float* __restrict__ xdbl, const float* __restrict__ Wdt,
                          const float* __restrict__ bdt, float* __restrict__ dtout)
{
    int idx = blockIdx.x * blockDim.x + threadIdx.x;    // T_TOK * DI
    int t = idx >> 7, d = idx & 127;
    float4 xr = __ldg((const float4*)(xdbl + (size_t)t * 36));
    float4 w  = __ldg((const float4*)(Wdt + d * 4));
    float v = xr.x * w.x + xr.y * w.y + xr.z * w.z + xr.w * w.w + __ldg(bdt + d);
    v = (v > 20.f) ? v : log1pf(expf(v));
    dtout[idx] = v;
}

#define UNPACK4(dst, i, v) { dst[4*(i)+0]=(v).x; dst[4*(i)+1]=(v).y; dst[4*(i)+2]=(v).z; dst[4*(i)+3]=(v).w; }

// ---------------- scan phase A: per-chunk zero-init scan ----------------
__global__ void __launch_bounds__(128) scanA_kernel(const float* __restrict__ dtp,
                                                    const float* __restrict__ xcp,
                                                    const float* __restrict__ xdbl,
                                                    const float* __restrict__ A2,
                                                    float* __restrict__ ypart,
                                                    float* __restrict__ hend,
                                                    float* __restrict__ dtsum)
{
    const int d   = threadIdx.x;
    const int seq = blockIdx.x >> 5;
    const int ch  = blockIdx.x & 31;
    const int t0  = seq * L_SEQ + ch * CLCH;

    float A2r[16], h[16];
    #pragma unroll
    for (int n = 0; n < 16; n++) { A2r[n] = A2[d * 16 + n]; h[n] = 0.f; }
    float S = 0.f;

    for (int tl = 0; tl < CLCH; tl++) {
        int t = t0 + tl;
        float dt = dtp[(size_t)t * DI + d];
        float xc = xcp[(size_t)t * DI + d];
        const float4* bc = (const float4*)(xdbl + (size_t)t * 36 + 4);
        float4 B0 = __ldg(bc + 0), B1 = __ldg(bc + 1), B2 = __ldg(bc + 2), B3 = __ldg(bc + 3);
        float4 C0 = __ldg(bc + 4), C1 = __ldg(bc + 5), C2 = __ldg(bc + 6), C3 = __ldg(bc + 7);
        float Bf[16], Cf[16];
        UNPACK4(Bf, 0, B0); UNPACK4(Bf, 1, B1); UNPACK4(Bf, 2, B2); UNPACK4(Bf, 3, B3);
        UNPACK4(Cf, 0, C0); UNPACK4(Cf, 1, C1); UNPACK4(Cf, 2, C2); UNPACK4(Cf, 3, C3);
        float dtx = dt * xc;
        float y = 0.f;
        #pragma unroll
        for (int n = 0; n < 16; n++) {
            float a = exp2f(dt * A2r[n]);
            h[n] = fmaf(a, h[n], dtx * Bf[n]);
            y = fmaf(h[n], Cf[n], y);
        }
        S += dt;
        ypart[(size_t)t * DI + d] = y;
    }
    size_t hb = ((size_t)blockIdx.x * DI + d) * 16;
    #pragma unroll
    for (int n = 0; n < 16; n++) hend[hb + n] = h[n];
    dtsum[(size_t)blockIdx.x * DI + d] = S;
}

// ---------------- scan phase B: sequential chunk combine ----------------
__global__ void __launch_bounds__(128) scanB_kernel(const float* __restrict__ A2,
                                                    const float* __restrict__ hend,
                                                    const float* __restrict__ dtsum,
                                                    float* __restrict__ h0out)
{
    const int d = threadIdx.x;
    const int seq = blockIdx.x;
    float A2r[16], h0[16];
    #pragma unroll
    for (int n = 0; n < 16; n++) { A2r[n] = A2[d * 16 + n]; h0[n] = 0.f; }
    for (int k = 0; k < NCH; k++) {
        size_t base = (((size_t)seq * NCH + k) * DI + d) * 16;
        #pragma unroll
        for (int n = 0; n < 16; n++) h0out[base + n] = h0[n];
        float S = dtsum[((size_t)seq * NCH + k) * DI + d];
        #pragma unroll
        for (int n = 0; n < 16; n++)
            h0[n] = fmaf(exp2f(S * A2r[n]), h0[n], hend[base + n]);
    }
}

// ---------------- scan phase C: state correction + gating ----------------
__global__ void __launch_bounds__(128) scanC_kernel(const float* __restrict__ dtp,
                                                    const float* __restrict__ xcp,
                                                    const float* __restrict__ zp,
                                                    const float* __restrict__ xdbl,
                                                    const float* __restrict__ A2,
                                                    const float* __restrict__ ypart,
                                                    const float* __restrict__ h0in,
                                                    const float* __restrict__ Dp,
                                                    float* __restrict__ yout)
{
    const int d   = threadIdx.x;
    const int seq = blockIdx.x >> 5;
    const int ch  = blockIdx.x & 31;
    const int t0  = seq * L_SEQ + ch * CLCH;

    float A2r[16], h0[16];
    size_t hb = ((size_t)blockIdx.x * DI + d) * 16;
    #pragma unroll
    for (int n = 0; n < 16; n++) { A2r[n] = A2[d * 16 + n]; h0[n] = h0in[hb + n]; }
    const float Dd = Dp[d];
    float S = 0.f;

    for (int tl = 0; tl < CLCH; tl++) {
        int t = t0 + tl;
        float dt = dtp[(size_t)t * DI + d];
        S += dt;
        float y = ypart[(size_t)t * DI + d];
        const float4* cc = (const float4*)(xdbl + (size_t)t * 36 + 20);
        float4 C0 = __ldg(cc + 0), C1 = __ldg(cc + 1), C2 = __ldg(cc + 2), C3 = __ldg(cc + 3);
        float Cf[16];
        UNPACK4(Cf, 0, C0); UNPACK4(Cf, 1, C1); UNPACK4(Cf, 2, C2); UNPACK4(Cf, 3, C3);
        #pragma unroll
        for (int n = 0; n < 16; n++)
            y = fmaf(exp2f(S * A2r[n]) * h0[n], Cf[n], y);
        float xc = xcp[(size_t)t * DI + d];
        float zs = zp[(size_t)t * DI + d];
        yout[(size_t)t * DI + d] = (y + xc * Dd) * zs;
    }
}

// ---------------- LayerNorm over DM=64 ----------------
__global__ void __launch_bounds__(256) ln2_kernel(const float* __restrict__ ym,
                                                  const float* __restrict__ g,
                                                  const float* __restrict__ bb,
                                                  float* __restrict__ yn)
{
    int t = blockIdx.x * 8 + (threadIdx.x >> 5);
    int lane = threadIdx.x & 31;
    float2 v = *(const float2*)(ym + (size_t)t * DM + lane * 2);
    float s = v.x + v.y;
    float s2 = v.x * v.x + v.y * v.y;
    #pragma unroll
    for (int o = 16; o; o >>= 1) {
        s  += __shfl_xor_sync(0xffffffffu, s, o);
        s2 += __shfl_xor_sync(0xffffffffu, s2, o);
    }
    float mean = s * (1.0f / 64.0f);
    float var  = s2 * (1.0f / 64.0f) - mean * mean;
    float rs   = rsqrtf(var + EPS);
    int c = lane * 2;
    float2 o;
    o.x = (v.x - mean) * rs * g[c]     + bb[c];
    o.y = (v.y - mean) * rs * g[c + 1] + bb[c + 1];
    *(float2*)(yn + (size_t)t * DM + c) = o;
}

// ---------------- rearrange ym2 (16,L,64) -> xi row-major (B*L, 256), c = d*4+chunk ----------------
__global__ void __launch_bounds__(256) rearrange_kernel(const float* __restrict__ ym2,
                                                        float* __restrict__ xi)
{
    __shared__ float sm[32][260];
    const int b  = blockIdx.y;
    const int l0 = blockIdx.x * 32;
    const int tid = threadIdx.x;
    #pragma unroll
    for (int chunk = 0; chunk < 4; chunk++) {
        int seq = chunk * 4 + b;
        const float* src = ym2 + ((size_t)seq * L_SEQ + l0) * DM;
        #pragma unroll
        for (int it = 0; it < 8; it++) {
            int idx = it * 256 + tid;          // 2048 = 32*64
            int ll = idx >> 6, d = idx & 63;
            sm[ll][d * 4 + chunk] = src[idx];
        }
    }
    __syncthreads();
    const size_t ob = ((size_t)b * L_SEQ + l0) * 256;
    #pragma unroll
    for (int it = 0; it < 32; it++)
        xi[ob + (size_t)it * 256 + tid] = sm[it][tid];
}

// ---------------- host ----------------
static float* sym(const void* s)
{
    void* p = nullptr;
    cudaGetSymbolAddress(&p, s);
    return (float*)p;
}

extern "C" void kernel_launch(void* const* d_in, const int* in_sizes, int n_in,
                              void* d_out, int out_size)
{
    const float* x        = (const float*)d_in[0];
    const float* gn       = (const float*)d_in[1];
    const float* bn       = (const float*)d_in[2];
    const float* gn1      = (const float*)d_in[3];
    const float* bn1      = (const float*)d_in[4];
    const float* W_in     = (const float*)d_in[5];
    const float* W_conv   = (const float*)d_in[6];
    const float* b_conv   = (const float*)d_in[7];
    const float* W_xproj  = (const float*)d_in[8];
    const float* W_dt     = (const float*)d_in[9];
    const float* b_dt     = (const float*)d_in[10];
    const float* A_log    = (const float*)d_in[11];
    const float* D_par    = (const float*)d_in[12];
    const float* W_outp   = (const float*)d_in[13];
    const float* skip_s   = (const float*)d_in[14];
    const float* W_fc1    = (const float*)d_in[15];
    const float* b_fc1    = (const float*)d_in[16];
    const float* W_fc2    = (const float*)d_in[17];
    const float* b_fc2    = (const float*)d_in[18];
    const float* W_out    = (const float*)d_in[19];
    const float* bn_g     = (const float*)d_in[20];
    const float* bn_b     = (const float*)d_in[21];
    const float* bn_mean  = (const float*)d_in[22];
    const float* bn_var   = (const float*)d_in[23];
    float* out = (float*)d_out;

    float* xs    = sym(g_xs);
    float* xcpre = sym(g_xcpre);
    float* z     = sym(g_z);
    float* xc    = sym(g_xc);
    float* xdbl  = sym(g_xdbl);
    float* dt    = sym(g_dt);
    float* ypart = sym(g_ypart);
    float* y     = sym(g_y);
    float* hend  = sym(g_hend);
    float* h0    = sym(g_h0);
    float* dtsum = sym(g_dtsum);
    float* ym    = sym(g_ym);
    float* yn    = sym(g_yn);
    float* h1    = sym(g_h1);
    float* ym2   = sym(g_ym2);
    float* xi    = sym(g_xi);
    float* A2    = sym(g_A2);

    EpiArgs e0 = { nullptr, nullptr, nullptr, nullptr, nullptr };

    // 1. A2 precompute
    a2_kernel<<<8, 256>>>(A_log, A2);
    // 2. LN over C + chunk split
    ln1_kernel<<<dim3(128, 4), 256>>>(x, gn, bn, xs);
    // 3. in-proj GEMM: xz = xs @ W_in^T ; split -> xcpre, silu(z)
    {
        EpiArgs ea = e0; ea.out2 = z;
        gemm_k<64, EPI_SPLIT><<<dim3(4, 1024), 256>>>(xs, W_in, xcpre, T_TOK, 256, ea);
    }
    // 4. depthwise causal conv + silu
    conv_kernel<<<(T_TOK * 32) / 256, 256>>>(xcpre, W_conv, b_conv, xc);
    // 5. x_dbl = xc @ W_xproj^T (N=36)
    gemm_k<128, EPI_STORE><<<dim3(1, 1024), 256>>>(xc, W_xproj, xdbl, T_TOK, 36, e0);
    // 6. dt = softplus(x_dbl[:, :4] @ W_dt^T + b_dt)
    dt_kernel<<<(T_TOK * DI) / 256, 256>>>(xdbl, W_dt, b_dt, dt);
    // 7-9. chunked selective scan
    scanA_kernel<<<NSEQ * NCH, 128>>>(dt, xc, xdbl, A2, ypart, hend, dtsum);
    scanB_kernel<<<NSEQ, 128>>>(A2, hend, dtsum, h0);
    scanC_kernel<<<NSEQ * NCH, 128>>>(dt, xc, z, xdbl, A2, ypart, h0, D_par, y);
    // 10. out-proj: ym = y @ W_outp^T
    gemm_k<128, EPI_STORE><<<dim3(1, 1024), 256>>>(y, W_outp, ym, T_TOK, 64, e0);
    // 11. LN over DM
    ln2_kernel<<<T_TOK / 8, 256>>>(ym, gn1, bn1, yn);
    // 12. fc1 + gelu
    {
        EpiArgs ea = e0; ea.b0 = b_fc1;
        gemm_k<64, EPI_GELU><<<dim3(4, 1024), 256>>>(yn, W_fc1, h1, T_TOK, 256, ea);
    }
    // 13. fc2 + bias + skip
    {
        EpiArgs ea = e0; ea.b0 = b_fc2; ea.b1 = xs; ea.b2 = skip_s;
        gemm_k<256, EPI_SKIP><<<dim3(1, 1024), 256>>>(h1, W_fc2, ym2, T_TOK, 64, ea);
    }
    // 14. channel interleave rearrange
    rearrange_kernel<<<dim3(128, 4), 256>>>(ym2, xi);
    // 15. final 256x256 GEMM + BN + silu, transposed store into d_out
    {
        EpiArgs ea = e0; ea.b0 = bn_g; ea.b1 = bn_b; ea.b2 = bn_mean; ea.b3 = bn_var;
        gemm_k<256, EPI_BN><<<dim3(4, 256), 256>>>(xi, W_out, out, B_IMG * L_SEQ, 256, ea);
    }
    (void)in_sizes; (void)n_in; (void)out_size;
}

// round 2
// speedup vs baseline: 1.3588x; 1.3588x over previous
#include <cuda_runtime.h>
#include <cstdint>

// Problem constants
#define B_IMG   4
#define C_CH    256
#define L_SEQ   4096
#define NSEQ    16
#define T_TOK   65536
#define DM      64
#define DI      128
#define NSTATE  16
#define CLCH    128
#define NCH     32
#define EPS     1e-5f

// ---------------- scratch ----------------
__device__ float g_xs   [T_TOK * DM];
__device__ float g_xcpre[T_TOK * DI];
__device__ float g_z    [T_TOK * DI];
__device__ float g_xc   [T_TOK * DI];
__device__ float g_xdbl [T_TOK * 36];
__device__ float g_dt   [T_TOK * DI];
__device__ float g_ypart[T_TOK * DI];
__device__ float g_y    [T_TOK * DI];
__device__ float g_hend [NSEQ * NCH * DI * NSTATE];
__device__ float g_h0   [NSEQ * NCH * DI * NSTATE];
__device__ float g_dtsum[NSEQ * NCH * DI];
__device__ float g_ym   [T_TOK * DM];
__device__ float g_yn   [T_TOK * DM];
__device__ float g_h1   [T_TOK * 256];
__device__ float g_ym2  [T_TOK * DM];
__device__ float g_xi   [B_IMG * L_SEQ * C_CH];
__device__ float g_A2   [DI * NSTATE];

__device__ __forceinline__ float siluf(float v) { return v / (1.0f + expf(-v)); }

__device__ __forceinline__ uint32_t f2tf(float f)
{
    uint32_t r;
    asm("cvt.rna.tf32.f32 %0, %1;" : "=r"(r) : "f"(f));
    return r;
}

// ---------------- A2 precompute ----------------
__global__ void a2_kernel(const float* __restrict__ A_log, float* __restrict__ A2)
{
    int i = blockIdx.x * blockDim.x + threadIdx.x;
    if (i < DI * NSTATE) A2[i] = -expf(A_log[i]) * 1.44269504088896340736f;
}

// ---------------- LayerNorm over C=256 + chunk rearrange ----------------
__global__ void __launch_bounds__(256) ln1_kernel(const float* __restrict__ x,
                                                  const float* __restrict__ g,
                                                  const float* __restrict__ bb,
                                                  float* __restrict__ xs)
{
    __shared__ float sm[32][257];
    const int b  = blockIdx.y;
    const int l0 = blockIdx.x * 32;
    const int lane = threadIdx.x & 31;
    const int w    = threadIdx.x >> 5;
    const float* xb = x + (size_t)b * C_CH * L_SEQ;

    for (int c = w; c < 256; c += 8)
        sm[lane][c] = xb[(size_t)c * L_SEQ + l0 + lane];
    __syncthreads();

    for (int tk = 0; tk < 4; tk++) {
        int l = w * 4 + tk;
        float s = 0.f, s2 = 0.f;
        #pragma unroll
        for (int j = 0; j < 8; j++) {
            float v = sm[l][lane + 32 * j];
            s += v; s2 += v * v;
        }
        #pragma unroll
        for (int o = 16; o; o >>= 1) {
            s  += __shfl_xor_sync(0xffffffffu, s, o);
            s2 += __shfl_xor_sync(0xffffffffu, s2, o);
        }
        float mean = s * (1.0f / 256.0f);
        float var  = s2 * (1.0f / 256.0f) - mean * mean;
        float rs   = rsqrtf(var + EPS);
        #pragma unroll
        for (int j = 0; j < 8; j++) {
            int c = lane + 32 * j;
            float v = (sm[l][c] - mean) * rs * g[c] + bb[c];
            int seq = (c >> 6) * 4 + b;
            int d   = c & 63;
            xs[((size_t)seq * L_SEQ + l0 + l) * DM + d] = v;
        }
    }
}

// ---------------- tf32 tensor-core GEMM: C = A(M,K) * W(N,K)^T ----------------
struct EpiArgs {
    const float* b0;
    const float* b1;
    const float* b2;
    const float* b3;
    float* out2;
};

#define EPI_STORE 0
#define EPI_SPLIT 1
#define EPI_GELU  2
#define EPI_SKIP  3
#define EPI_BN    4

__device__ __forceinline__ void mma_tf32(float* c, const uint32_t* a, const uint32_t* b)
{
    asm volatile(
        "mma.sync.aligned.m16n8k8.row.col.f32.tf32.tf32.f32 "
        "{%0,%1,%2,%3}, {%4,%5,%6,%7}, {%8,%9}, {%0,%1,%2,%3};"
        : "+f"(c[0]), "+f"(c[1]), "+f"(c[2]), "+f"(c[3])
        : "r"(a[0]), "r"(a[1]), "r"(a[2]), "r"(a[3]), "r"(b[0]), "r"(b[1]));
}

// Block tile 128(M) x 64(N) x 32(K). 256 threads = 8 warps (4 M x 2 N),
// warp tile 32x32 = 2 x 4 m16n8k8 tiles.
// Smem holds fragment-permuted, k8-XOR-swizzled tf32 operands.
template<int K, int EPI>
__global__ void __launch_bounds__(256) gemm_mma(const float* __restrict__ A,
                                                const float* __restrict__ W,
                                                float* __restrict__ C,
                                                int M, int N, EpiArgs ea)
{
    __shared__ uint32_t As[2][4096];   // [k8][mt(8)][lane(32)][reg(4)]
    __shared__ uint32_t Bs[2][2048];   // [k8][nt(8)][lane(32)][reg(2)]

    const int tid  = threadIdx.x;
    const int bm   = blockIdx.y * 128;
    const int bn   = blockIdx.x * 64;
    const int lane = tid & 31;
    const int wid  = tid >> 5;
    const int wm   = wid >> 1;
    const int wn   = wid & 1;

    // writer decomposition
    const int fq  = tid & 7;            // float4 column within 32-wide k-slab
    const int r0  = tid >> 3;           // 0..31
    const int k8w = fq >> 1;
    const int khf = fq & 1;

    float4 aL[4];
    float4 bL[2];

    float acc[2][4][4];
    #pragma unroll
    for (int mi = 0; mi < 2; mi++)
        #pragma unroll
        for (int ni = 0; ni < 4; ni++)
            #pragma unroll
            for (int q = 0; q < 4; q++) acc[mi][ni][q] = 0.f;

    auto loadG = [&](int kt) {
        const float* Ab = A + (size_t)bm * K + kt * 32 + fq * 4;
        #pragma unroll
        for (int p = 0; p < 4; p++)
            aL[p] = *(const float4*)(Ab + (size_t)(r0 + p * 32) * K);
        const float* Wb = W + kt * 32 + fq * 4;
        #pragma unroll
        for (int p = 0; p < 2; p++) {
            int n = bn + r0 + p * 32;
            if (n < N) bL[p] = *(const float4*)(Wb + (size_t)n * K);
            else       bL[p] = make_float4(0.f, 0.f, 0.f, 0.f);
        }
    };

    auto storeS = [&](int buf) {
        #pragma unroll
        for (int p = 0; p < 4; p++) {
            int r  = r0 + p * 32;
            int g  = r & 7;
            int mt = r >> 4;
            int reg = ((r >> 3) & 1) + (khf << 1);
            uint32_t* dst = &As[buf][(((k8w << 3) + mt) * 32 + (g << 2)) * 4 + reg];
            float v[4] = {aL[p].x, aL[p].y, aL[p].z, aL[p].w};
            #pragma unroll
            for (int j = 0; j < 4; j++)
                dst[(j ^ k8w) << 2] = f2tf(v[j]);
        }
        #pragma unroll
        for (int p = 0; p < 2; p++) {
            int n  = r0 + p * 32;
            int gn = n & 7;
            int nt = n >> 3;
            uint32_t* dst = &Bs[buf][(((k8w << 3) + nt) * 32 + (gn << 2)) * 2 + khf];
            float v[4] = {bL[p].x, bL[p].y, bL[p].z, bL[p].w};
            #pragma unroll
            for (int j = 0; j < 4; j++)
                dst[(j ^ k8w) << 1] = f2tf(v[j]);
        }
    };

    loadG(0);
    storeS(0);
    __syncthreads();

    const int NK = K / 32;
    for (int kt = 0; kt < NK; kt++) {
        int cur = kt & 1;
        if (kt + 1 < NK) loadG(kt + 1);
        #pragma unroll
        for (int k8 = 0; k8 < 4; k8++) {
            uint32_t af[2][4];
            #pragma unroll
            for (int mi = 0; mi < 2; mi++) {
                uint4 v = *(const uint4*)&As[cur][(((k8 << 3) + wm * 2 + mi) * 32 + (lane ^ k8)) * 4];
                af[mi][0] = v.x; af[mi][1] = v.y; af[mi][2] = v.z; af[mi][3] = v.w;
            }
            uint32_t bf[4][2];
            #pragma unroll
            for (int ni = 0; ni < 4; ni++) {
                uint2 v = *(const uint2*)&Bs[cur][(((k8 << 3) + wn * 4 + ni) * 32 + (lane ^ k8)) * 2];
                bf[ni][0] = v.x; bf[ni][1] = v.y;
            }
            #pragma unroll
            for (int mi = 0; mi < 2; mi++)
                #pragma unroll
                for (int ni = 0; ni < 4; ni++)
                    mma_tf32(acc[mi][ni], af[mi], bf[ni]);
        }
        if (kt + 1 < NK) storeS(cur ^ 1);
        __syncthreads();
    }

    // epilogue
    const int g   = lane >> 2;
    const int tig = lane & 3;
    #pragma unroll
    for (int mi = 0; mi < 2; mi++) {
        #pragma unroll
        for (int half = 0; half < 2; half++) {
            int m = bm + wm * 32 + mi * 16 + g + half * 8;
            #pragma unroll
            for (int ni = 0; ni < 4; ni++) {
                int n = bn + wn * 32 + ni * 8 + tig * 2;
                if (n >= N) continue;
                float v0 = acc[mi][ni][half * 2 + 0];
                float v1 = acc[mi][ni][half * 2 + 1];
                if (EPI == EPI_STORE) {
                    float2 o = {v0, v1};
                    *(float2*)&C[(size_t)m * N + n] = o;
                } else if (EPI == EPI_SPLIT) {
                    if (n < 128) {
                        float2 o = {v0, v1};
                        *(float2*)&C[(size_t)m * 128 + n] = o;
                    } else {
                        float2 o = {siluf(v0), siluf(v1)};
                        *(float2*)&ea.out2[(size_t)m * 128 + (n - 128)] = o;
                    }
                } else if (EPI == EPI_GELU) {
                    v0 += ea.b0[n];
                    v1 += ea.b0[n + 1];
                    v0 = 0.5f * v0 * (1.0f + erff(v0 * 0.70710678118654752f));
                    v1 = 0.5f * v1 * (1.0f + erff(v1 * 0.70710678118654752f));
                    float2 o = {v0, v1};
                    *(float2*)&C[(size_t)m * N + n] = o;
                } else if (EPI == EPI_SKIP) {
                    float ss = ea.b2[0];
                    v0 += ea.b0[n]     + ss * ea.b1[(size_t)m * DM + n];
                    v1 += ea.b0[n + 1] + ss * ea.b1[(size_t)m * DM + n + 1];
                    float2 o = {v0, v1};
                    *(float2*)&C[(size_t)m * N + n] = o;
                } else { // EPI_BN
                    int bb = m >> 12, l = m & 4095;
                    float sc0 = ea.b0[n]     * rsqrtf(ea.b3[n]     + EPS);
                    float sc1 = ea.b0[n + 1] * rsqrtf(ea.b3[n + 1] + EPS);
                    float sh0 = ea.b1[n]     - ea.b2[n]     * sc0;
                    float sh1 = ea.b1[n + 1] - ea.b2[n + 1] * sc1;
                    C[(((size_t)bb * 256 + n)     << 12) + l] = siluf(v0 * sc0 + sh0);
                    C[(((size_t)bb * 256 + n + 1) << 12) + l] = siluf(v1 * sc1 + sh1);
                }
            }
        }
    }
}

// ---------------- depthwise causal conv (KC=4) + bias + silu ----------------
__global__ void conv_kernel(const float* __restrict__ xcpre, const float* __restrict__ Wc,
                            const float* __restrict__ bc, float* __restrict__ xcout)
{
    int idx = blockIdx.x * blockDim.x + threadIdx.x;
    int t = idx >> 5;
    int q = (idx & 31) << 2;
    int l = t & (L_SEQ - 1);

    float wjc[4][4];
    #pragma unroll
    for (int c = 0; c < 4; c++) {
        float4 w = __ldg((const float4*)(Wc + (q + c) * 4));
        wjc[0][c] = w.x; wjc[1][c] = w.y; wjc[2][c] = w.z; wjc[3][c] = w.w;
    }
    float4 b4 = __ldg((const float4*)(bc + q));
    float o0 = b4.x, o1 = b4.y, o2 = b4.z, o3 = b4.w;
    #pragma unroll
    for (int j = 0; j < 4; j++) {
        int lj = l - 3 + j;
        if (lj >= 0) {
            float4 v = __ldg((const float4*)(xcpre + (size_t)(t - 3 + j) * DI + q));
            o0 = fmaf(v.x, wjc[j][0], o0);
            o1 = fmaf(v.y, wjc[j][1], o1);
            o2 = fmaf(v.z, wjc[j][2], o2);
            o3 = fmaf(v.w, wjc[j][3], o3);
        }
    }
    float4 out = make_float4(siluf(o0), siluf(o1), siluf(o2), siluf(o3));
    *(float4*)(xcout + (size_t)t * DI + q) = out;
}

// ---------------- dt = softplus(x_dbl[:, :4] @ W_dt^T + b_dt) ----------------
__global__ void dt_kernel(const float* __restrict__ xdbl, const float* __restrict__ Wdt,
                          const float* __restrict__ bdt, float* __restrict__ dtout)
{
    int idx = blockIdx.x * blockDim.x + threadIdx.x;
    int t = idx >> 7, d = idx & 127;
    float4 xr = __ldg((const float4*)(xdbl + (size_t)t * 36));
    float4 w  = __ldg((const float4*)(Wdt + d * 4));
    float v = xr.x * w.x + xr.y * w.y + xr.z * w.z + xr.w * w.w + __ldg(bdt + d);
    v = (v > 20.f) ? v : log1pf(expf(v));
    dtout[idx] = v;
}

#define UNPACK4(dst, i, v) { dst[4*(i)+0]=(v).x; dst[4*(i)+1]=(v).y; dst[4*(i)+2]=(v).z; dst[4*(i)+3]=(v).w; }

// ---------------- scan phase A ----------------
__global__ void __launch_bounds__(128) scanA_kernel(const float* __restrict__ dtp,
                                                    const float* __restrict__ xcp,
                                                    const float* __restrict__ xdbl,
                                                    const float* __restrict__ A2,
                                                    float* __restrict__ ypart,
                                                    float* __restrict__ hend,
                                                    float* __restrict__ dtsum)
{
    const int d   = threadIdx.x;
    const int seq = blockIdx.x >> 5;
    const int ch  = blockIdx.x & 31;
    const int t0  = seq * L_SEQ + ch * CLCH;

    float A2r[16], h[16];
    #pragma unroll
    for (int n = 0; n < 16; n++) { A2r[n] = A2[d * 16 + n]; h[n] = 0.f; }
    float S = 0.f;

    for (int tl = 0; tl < CLCH; tl++) {
        int t = t0 + tl;
        float dt = dtp[(size_t)t * DI + d];
        float xc = xcp[(size_t)t * DI + d];
        const float4* bc = (const float4*)(xdbl + (size_t)t * 36 + 4);
        float4 B0 = __ldg(bc + 0), B1 = __ldg(bc + 1), B2 = __ldg(bc + 2), B3 = __ldg(bc + 3);
        float4 C0 = __ldg(bc + 4), C1 = __ldg(bc + 5), C2 = __ldg(bc + 6), C3 = __ldg(bc + 7);
        float Bf[16], Cf[16];
        UNPACK4(Bf, 0, B0); UNPACK4(Bf, 1, B1); UNPACK4(Bf, 2, B2); UNPACK4(Bf, 3, B3);
        UNPACK4(Cf, 0, C0); UNPACK4(Cf, 1, C1); UNPACK4(Cf, 2, C2); UNPACK4(Cf, 3, C3);
        float dtx = dt * xc;
        float y = 0.f;
        #pragma unroll
        for (int n = 0; n < 16; n++) {
            float a = exp2f(dt * A2r[n]);
            h[n] = fmaf(a, h[n], dtx * Bf[n]);
            y = fmaf(h[n], Cf[n], y);
        }
        S += dt;
        ypart[(size_t)t * DI + d] = y;
    }
    size_t hb = ((size_t)blockIdx.x * DI + d) * 16;
    #pragma unroll
    for (int n = 0; n < 16; n++) hend[hb + n] = h[n];
    dtsum[(size_t)blockIdx.x * DI + d] = S;
}

// ---------------- scan phase B ----------------
__global__ void __launch_bounds__(128) scanB_kernel(const float* __restrict__ A2,
                                                    const float* __restrict__ hend,
                                                    const float* __restrict__ dtsum,
                                                    float* __restrict__ h0out)
{
    const int d = threadIdx.x;
    const int seq = blockIdx.x;
    float A2r[16], h0[16];
    #pragma unroll
    for (int n = 0; n < 16; n++) { A2r[n] = A2[d * 16 + n]; h0[n] = 0.f; }
    for (int k = 0; k < NCH; k++) {
        size_t base = (((size_t)seq * NCH + k) * DI + d) * 16;
        #pragma unroll
        for (int n = 0; n < 16; n++) h0out[base + n] = h0[n];
        float S = dtsum[((size_t)seq * NCH + k) * DI + d];
        #pragma unroll
        for (int n = 0; n < 16; n++)
            h0[n] = fmaf(exp2f(S * A2r[n]), h0[n], hend[base + n]);
    }
}

// ---------------- scan phase C ----------------
__global__ void __launch_bounds__(128) scanC_kernel(const float* __restrict__ dtp,
                                                    const float* __restrict__ xcp,
                                                    const float* __restrict__ zp,
                                                    const float* __restrict__ xdbl,
                                                    const float* __restrict__ A2,
                                                    const float* __restrict__ ypart,
                                                    const float* __restrict__ h0in,
                                                    const float* __restrict__ Dp,
                                                    float* __restrict__ yout)
{
    const int d   = threadIdx.x;
    const int seq = blockIdx.x >> 5;
    const int ch  = blockIdx.x & 31;
    const int t0  = seq * L_SEQ + ch * CLCH;

    float A2r[16], h0[16];
    size_t hb = ((size_t)blockIdx.x * DI + d) * 16;
    #pragma unroll
    for (int n = 0; n < 16; n++) { A2r[n] = A2[d * 16 + n]; h0[n] = h0in[hb + n]; }
    const float Dd = Dp[d];
    float S = 0.f;

    for (int tl = 0; tl < CLCH; tl++) {
        int t = t0 + tl;
        float dt = dtp[(size_t)t * DI + d];
        S += dt;
        float y = ypart[(size_t)t * DI + d];
        const float4* cc = (const float4*)(xdbl + (size_t)t * 36 + 20);
        float4 C0 = __ldg(cc + 0), C1 = __ldg(cc + 1), C2 = __ldg(cc + 2), C3 = __ldg(cc + 3);
        float Cf[16];
        UNPACK4(Cf, 0, C0); UNPACK4(Cf, 1, C1); UNPACK4(Cf, 2, C2); UNPACK4(Cf, 3, C3);
        #pragma unroll
        for (int n = 0; n < 16; n++)
            y = fmaf(exp2f(S * A2r[n]) * h0[n], Cf[n], y);
        float xc = xcp[(size_t)t * DI + d];
        float zs = zp[(size_t)t * DI + d];
        yout[(size_t)t * DI + d] = (y + xc * Dd) * zs;
    }
}

// ---------------- LayerNorm over DM=64 ----------------
__global__ void __launch_bounds__(256) ln2_kernel(const float* __restrict__ ym,
                                                  const float* __restrict__ g,
                                                  const float* __restrict__ bb,
                                                  float* __restrict__ yn)
{
    int t = blockIdx.x * 8 + (threadIdx.x >> 5);
    int lane = threadIdx.x & 31;
    float2 v = *(const float2*)(ym + (size_t)t * DM + lane * 2);
    float s = v.x + v.y;
    float s2 = v.x * v.x + v.y * v.y;
    #pragma unroll
    for (int o = 16; o; o >>= 1) {
        s  += __shfl_xor_sync(0xffffffffu, s, o);
        s2 += __shfl_xor_sync(0xffffffffu, s2, o);
    }
    float mean = s * (1.0f / 64.0f);
    float var  = s2 * (1.0f / 64.0f) - mean * mean;
    float rs   = rsqrtf(var + EPS);
    int c = lane * 2;
    float2 o;
    o.x = (v.x - mean) * rs * g[c]     + bb[c];
    o.y = (v.y - mean) * rs * g[c + 1] + bb[c + 1];
    *(float2*)(yn + (size_t)t * DM + c) = o;
}

// ---------------- rearrange ----------------
__global__ void __launch_bounds__(256) rearrange_kernel(const float* __restrict__ ym2,
                                                        float* __restrict__ xi)
{
    __shared__ float sm[32][260];
    const int b  = blockIdx.y;
    const int l0 = blockIdx.x * 32;
    const int tid = threadIdx.x;
    #pragma unroll
    for (int chunk = 0; chunk < 4; chunk++) {
        int seq = chunk * 4 + b;
        const float* src = ym2 + ((size_t)seq * L_SEQ + l0) * DM;
        #pragma unroll
        for (int it = 0; it < 8; it++) {
            int idx = it * 256 + tid;
            int ll = idx >> 6, d = idx & 63;
            sm[ll][d * 4 + chunk] = src[idx];
        }
    }
    __syncthreads();
    const size_t ob = ((size_t)b * L_SEQ + l0) * 256;
    #pragma unroll
    for (int it = 0; it < 32; it++)
        xi[ob + (size_t)it * 256 + tid] = sm[it][tid];
}

// ---------------- host ----------------
static float* sym(const void* s)
{
    void* p = nullptr;
    cudaGetSymbolAddress(&p, s);
    return (float*)p;
}

extern "C" void kernel_launch(void* const* d_in, const int* in_sizes, int n_in,
                              void* d_out, int out_size)
{
    const float* x        = (const float*)d_in[0];
    const float* gn       = (const float*)d_in[1];
    const float* bn       = (const float*)d_in[2];
    const float* gn1      = (const float*)d_in[3];
    const float* bn1      = (const float*)d_in[4];
    const float* W_in     = (const float*)d_in[5];
    const float* W_conv   = (const float*)d_in[6];
    const float* b_conv   = (const float*)d_in[7];
    const float* W_xproj  = (const float*)d_in[8];
    const float* W_dt     = (const float*)d_in[9];
    const float* b_dt     = (const float*)d_in[10];
    const float* A_log    = (const float*)d_in[11];
    const float* D_par    = (const float*)d_in[12];
    const float* W_outp   = (const float*)d_in[13];
    const float* skip_s   = (const float*)d_in[14];
    const float* W_fc1    = (const float*)d_in[15];
    const float* b_fc1    = (const float*)d_in[16];
    const float* W_fc2    = (const float*)d_in[17];
    const float* b_fc2    = (const float*)d_in[18];
    const float* W_out    = (const float*)d_in[19];
    const float* bn_g     = (const float*)d_in[20];
    const float* bn_b     = (const float*)d_in[21];
    const float* bn_mean  = (const float*)d_in[22];
    const float* bn_var   = (const float*)d_in[23];
    float* out = (float*)d_out;

    float* xs    = sym(g_xs);
    float* xcpre = sym(g_xcpre);
    float* z     = sym(g_z);
    float* xc    = sym(g_xc);
    float* xdbl  = sym(g_xdbl);
    float* dt    = sym(g_dt);
    float* ypart = sym(g_ypart);
    float* y     = sym(g_y);
    float* hend  = sym(g_hend);
    float* h0    = sym(g_h0);
    float* dtsum = sym(g_dtsum);
    float* ym    = sym(g_ym);
    float* yn    = sym(g_yn);
    float* h1    = sym(g_h1);
    float* ym2   = sym(g_ym2);
    float* xi    = sym(g_xi);
    float* A2    = sym(g_A2);

    EpiArgs e0 = { nullptr, nullptr, nullptr, nullptr, nullptr };

    a2_kernel<<<8, 256>>>(A_log, A2);
    ln1_kernel<<<dim3(128, 4), 256>>>(x, gn, bn, xs);
    // in-proj: xz = xs @ W_in^T ; split -> xcpre, silu(z)
    {
        EpiArgs ea = e0; ea.out2 = z;
        gemm_mma<64, EPI_SPLIT><<<dim3(4, 512), 256>>>(xs, W_in, xcpre, T_TOK, 256, ea);
    }
    conv_kernel<<<(T_TOK * 32) / 256, 256>>>(xcpre, W_conv, b_conv, xc);
    // x_dbl = xc @ W_xproj^T (N=36)
    gemm_mma<128, EPI_STORE><<<dim3(1, 512), 256>>>(xc, W_xproj, xdbl, T_TOK, 36, e0);
    dt_kernel<<<(T_TOK * DI) / 256, 256>>>(xdbl, W_dt, b_dt, dt);
    scanA_kernel<<<NSEQ * NCH, 128>>>(dt, xc, xdbl, A2, ypart, hend, dtsum);
    scanB_kernel<<<NSEQ, 128>>>(A2, hend, dtsum, h0);
    scanC_kernel<<<NSEQ * NCH, 128>>>(dt, xc, z, xdbl, A2, ypart, h0, D_par, y);
    // out-proj: ym = y @ W_outp^T
    gemm_mma<128, EPI_STORE><<<dim3(1, 512), 256>>>(y, W_outp, ym, T_TOK, 64, e0);
    ln2_kernel<<<T_TOK / 8, 256>>>(ym, gn1, bn1, yn);
    // fc1 + gelu
    {
        EpiArgs ea = e0; ea.b0 = b_fc1;
        gemm_mma<64, EPI_GELU><<<dim3(4, 512), 256>>>(yn, W_fc1, h1, T_TOK, 256, ea);
    }
    // fc2 + bias + skip
    {
        EpiArgs ea = e0; ea.b0 = b_fc2; ea.b1 = xs; ea.b2 = skip_s;
        gemm_mma<256, EPI_SKIP><<<dim3(1, 512), 256>>>(h1, W_fc2, ym2, T_TOK, 64, ea);
    }
    rearrange_kernel<<<dim3(128, 4), 256>>>(ym2, xi);
    // final 256x256 GEMM + BN + silu, transposed store
    {
        EpiArgs ea = e0; ea.b0 = bn_g; ea.b1 = bn_b; ea.b2 = bn_mean; ea.b3 = bn_var;
        gemm_mma<256, EPI_BN><<<dim3(4, 128), 256>>>(xi, W_out, out, B_IMG * L_SEQ, 256, ea);
    }
    (void)in_sizes; (void)n_in; (void)out_size;
}